// round 10
// baseline (speedup 1.0000x reference)
#include <cuda_runtime.h>
#include <cuda_bf16.h>
#include <cstdint>

// Problem constants
#define Bb 4
#define Nn 16384
#define Cc 128
#define Mm 1024
#define Kk 32
#define COLSX (Bb*Mm*Kk)          // 131072
#define R2c 0.16f
#define NBLK 1024                  // column tiles per GEMM (COLSX/128)

// -------------------- scratch (__device__ globals; no allocations) ---------
__device__ float  g_featT[(size_t)Bb*Nn*Cc];       // (B,N,C)
__device__ float4 g_xyz4[(size_t)Bb*Nn];           // packed xyz
__device__ float  g_newxyz[Bb*Mm*3];
__device__ int    g_idx[Bb*Mm*Kk];
__device__ uint4  g_W1bf[5120];                    // W1 swizzled bf16 hi/lo smem image (80 KB)
__device__ float  g_Y1[(size_t)COLSX*128];         // [col][cout]
__device__ float  g_Y2[(size_t)COLSX*128];
__device__ float2 g_mm[(size_t)Bb*Mm*256];         // [bm][cout] (max,min) over K
__device__ float2 g_part[(size_t)256*NBLK];
__device__ float2 g_aff[256];

// -------------------- helpers ----------------------------------------------
__device__ __forceinline__ uint32_t smem_u32(const void* p){
    uint32_t a;
    asm("{ .reg .u64 t; cvta.to.shared.u64 t, %1; cvt.u32.u64 %0, t; }" : "=r"(a) : "l"(p));
    return a;
}
__device__ __forceinline__ void ldm4(uint32_t* r, uint32_t addr){
    asm volatile("ldmatrix.sync.aligned.m8n8.x4.shared.b16 {%0,%1,%2,%3}, [%4];"
        : "=r"(r[0]), "=r"(r[1]), "=r"(r[2]), "=r"(r[3]) : "r"(addr));
}
__device__ __forceinline__ void mma_bf16(float* d, const uint32_t* a, const uint32_t* b){
    asm volatile("mma.sync.aligned.m16n8k16.row.col.f32.bf16.bf16.f32 "
        "{%0,%1,%2,%3}, {%4,%5,%6,%7}, {%8,%9}, {%0,%1,%2,%3};"
        : "+f"(d[0]), "+f"(d[1]), "+f"(d[2]), "+f"(d[3])
        : "r"(a[0]), "r"(a[1]), "r"(a[2]), "r"(a[3]), "r"(b[0]), "r"(b[1]));
}
// split 8 floats into hi/lo bf16 quads
__device__ __host__ __forceinline__ void cvt8(const float* f, uint4& H, uint4& L){
    uint32_t hh[4], ll[4];
    #pragma unroll
    for (int i = 0; i < 4; i++){
        __nv_bfloat162 h = __floats2bfloat162_rn(f[2*i], f[2*i+1]);
        float r0 = f[2*i]   - __low2float(h);
        float r1 = f[2*i+1] - __high2float(h);
        __nv_bfloat162 l = __floats2bfloat162_rn(r0, r1);
        hh[i] = *(uint32_t*)&h;
        ll[i] = *(uint32_t*)&l;
    }
    H = make_uint4(hh[0], hh[1], hh[2], hh[3]);
    L = make_uint4(ll[0], ll[1], ll[2], ll[3]);
}

// -------------------- 1. transpose features (B,C,N)->(B,N,C) ---------------
__global__ void transpose_kernel(const float* __restrict__ f){
    __shared__ float tile[32][33];
    const int b  = blockIdx.z;
    const int c0 = blockIdx.y << 5;
    const int n0 = blockIdx.x << 5;
    const int tx = threadIdx.x, ty = threadIdx.y;
    #pragma unroll
    for (int j = 0; j < 32; j += 8)
        tile[ty + j][tx] = f[((size_t)(b*Cc + c0 + ty + j))*Nn + n0 + tx];
    __syncthreads();
    #pragma unroll
    for (int j = 0; j < 32; j += 8)
        g_featT[((size_t)(b*Nn + n0 + ty + j))*Cc + c0 + tx] = tile[tx][ty + j];
}

// -------------------- 2. small prep: xyz4 + W1 bf16 image + newxyz ---------
__global__ void small_prep_kernel(const float* __restrict__ xyz,
                                  const int* __restrict__ indices,
                                  const float* __restrict__ w1,
                                  float* __restrict__ out){
    int t = blockIdx.x*256 + threadIdx.x;
    if (t < Bb*Nn){
        float4 v; v.x = xyz[t*3+0]; v.y = xyz[t*3+1]; v.z = xyz[t*3+2]; v.w = 0.f;
        g_xyz4[t] = v;
    }
    if (t < 2560){                       // W1 image: 5 chunks x 128 rows x 4 octs
        int c = t >> 9, rem = t & 511;
        int m = rem >> 2, o = rem & 3;
        int k0 = c*32 + o*8;
        float f[8];
        #pragma unroll
        for (int i = 0; i < 8; i++){
            int kk = k0 + i;
            float v = 0.f;
            if (kk < 128)      v = w1[m*131 + 3 + kk];
            else if (kk < 131) v = w1[m*131 + (kk - 128)];
            f[i] = v;
        }
        uint4 H, L; cvt8(f, H, L);
        int base = c*1024 + m*8;
        g_W1bf[base + (o       ^ (m & 7))] = H;
        g_W1bf[base + ((o + 4) ^ (m & 7))] = L;
    }
    if (t < Bb*Mm){
        int i = indices[t];
        const float* p = xyz + ((size_t)(t >> 10)*Nn + i)*3;
        float x = p[0], y = p[1], z = p[2];
        g_newxyz[t*3+0] = x; g_newxyz[t*3+1] = y; g_newxyz[t*3+2] = z;
        out[t*3+0] = x; out[t*3+1] = y; out[t*3+2] = z;
    }
}

// -------------------- 3. ball query: 16 warps/query + ordered merge --------
__global__ __launch_bounds__(512) void ballquery_kernel(){
    const int q = blockIdx.x;
    const int b = q >> 10;
    const int warp = threadIdx.x >> 5;
    const int lane = threadIdx.x & 31;
    __shared__ int cand[16][33];
    __shared__ int cnts[16];

    const float qx = g_newxyz[q*3+0];
    const float qy = g_newxyz[q*3+1];
    const float qz = g_newxyz[q*3+2];
    const float4* bp = g_xyz4 + (size_t)b*Nn;
    const int seg0 = warp << 10;

    int cnt = 0;
    for (int base = 0; base < 1024; base += 32){
        int n = seg0 + base + lane;
        float4 p = __ldg(bp + n);
        float dx = __fadd_rn(qx, -p.x), dy = __fadd_rn(qy, -p.y), dz = __fadd_rn(qz, -p.z);
        float d2 = __fadd_rn(__fadd_rn(__fmul_rn(dx,dx), __fmul_rn(dy,dy)), __fmul_rn(dz,dz));
        bool w = d2 < R2c;
        unsigned mask = __ballot_sync(0xffffffffu, w);
        int pre = __popc(mask & ((1u << lane) - 1u));
        if (w && cnt + pre < Kk) cand[warp][cnt + pre] = n;
        cnt += __popc(mask);
        if (cnt >= Kk) break;
    }
    if (lane == 0) cnts[warp] = cnt < Kk ? cnt : Kk;
    __syncthreads();

    if (warp == 0){
        int acc = 0, sel = -1, off = 0, first = -1;
        #pragma unroll
        for (int s = 0; s < 16; s++){
            int cs = cnts[s];
            if (sel < 0 && lane < acc + cs){ sel = s; off = lane - acc; }
            if (first < 0 && cs > 0) first = s;
            acc += cs;
        }
        int v = (sel >= 0) ? cand[sel][off]
                           : (first >= 0 ? cand[first][0] : 0);
        g_idx[q*Kk + lane] = v;
    }
}

// -------------------- 4. mma.sync bf16-split GEMM ---------------------------
// ROWS x 128 block tile, warp tile 64x64, ROWS threads (4 or 8 warps).
// A (weights) resident in smem (built once); B streamed through ONE 16 KB
// buffer at 16-k half-phase granularity (parity ping-pong, 1 bar/phase).
// Grid is (NBLK, 1) for all layers (gemm3 merged: ROWS=256).
#define OFF_AFF  0
#define OFF_PART 1024
#define OFF_IDX  5120
#define OFF_XYZ  5632
#define OFF_SA   8192
#define OFF_C    8192
#define CPITCH   132

template<int ROWS, int NPH, int KA, int KSOUT, bool ACT, bool GATHER, bool FINAL, bool AIMG, bool LASTHI>
__global__ __launch_bounds__(ROWS, ROWS == 128 ? 2 : 1)
void mma_gemm(const float* __restrict__ Asrc, const float* __restrict__ Bsrc,
              const float* __restrict__ bias, float* __restrict__ Y)
{
    constexpr int NC = (NPH + 1) / 2;
    constexpr int OFF_SB = OFF_SA + NC*ROWS*128;
    constexpr int BIT = 256 / ROWS;          // B-fill iterations per thread
    extern __shared__ char smem[];
    const uint32_t sb = smem_u32(smem);
    const int tid = threadIdx.x, wid = tid >> 5, lane = tid & 31;
    const int cb = blockIdx.x << 7;
    const int m0  = (wid >> 1) << 6;
    const int n0w = (wid & 1) << 6;

    float* afs   = (float*)(smem + OFF_AFF);
    int*   sidx  = (int*)(smem + OFF_IDX);
    float4* sxyz = (float4*)(smem + OFF_XYZ);
    const size_t bBase = (size_t)(cb >> 15)*Nn;

    if (ACT && tid < 128) ((float2*)afs)[tid] = g_aff[tid];
    if (GATHER && tid < 128){
        int i = g_idx[cb + tid];
        sidx[tid] = i;
        float4 p = g_xyz4[bBase + i];
        const int bm = (cb + tid) >> 5;
        const float* q = g_newxyz + (size_t)bm*3;
        float4 r; r.x = p.x - q[0]; r.y = p.y - q[1]; r.z = p.z - q[2]; r.w = 0.f;
        sxyz[tid] = r;
    }
    __syncthreads();

    float fB[BIT][8];
    auto PREF_B = [&](int p){
        if (GATHER && p == 8) return;
        #pragma unroll
        for (int it = 0; it < BIT; it++){
            const int s = tid + it*ROWS;
            const int n = s >> 1, h = s & 1;
            const float* src = GATHER
                ? g_featT + ((bBase + (size_t)sidx[n]) << 7) + p*16 + h*8
                : Bsrc + (size_t)(cb + n)*KA + p*16 + h*8;
            *(float4*)&fB[it][0] = __ldg((const float4*)src);
            *(float4*)&fB[it][4] = __ldg((const float4*)(src + 4));
        }
    };
    auto CVST_B = [&](int p){
        const int t = p & 1;
        const bool hion = LASTHI && (p == NPH - 1);
        #pragma unroll
        for (int it = 0; it < BIT; it++){
            const int s = tid + it*ROWS;
            const int n = s >> 1, h = s & 1;
            float f[8];
            if (GATHER && p == 8){
                #pragma unroll
                for (int i = 0; i < 8; i++) f[i] = 0.f;
                if (h == 0){ float4 xr = sxyz[n]; f[0] = xr.x; f[1] = xr.y; f[2] = xr.z; }
            } else {
                #pragma unroll
                for (int i = 0; i < 8; i++) f[i] = fB[it][i];
                if (ACT){
                    #pragma unroll
                    for (int i = 0; i < 8; i++){
                        const int k = p*16 + h*8 + i;
                        f[i] = fmaxf(fmaf(afs[2*k], f[i], afs[2*k+1]), 0.f);
                    }
                }
            }
            uint4 H, L; cvt8(f, H, L);
            char* base = smem + OFF_SB + (n << 7);
            const int ho = 2*t + h;
            *(uint4*)(base + (uint32_t)(((ho    ) ^ (n & 7)) << 4)) = H;
            if (!hion)
                *(uint4*)(base + (uint32_t)(((ho + 4) ^ (n & 7)) << 4)) = L;
        }
    };

    PREF_B(0);

    // build resident A
    if (AIMG){
        uint4* dst = (uint4*)(smem + OFF_SA);
        #pragma unroll 4
        for (int i = tid; i < NC*ROWS*8; i += ROWS) dst[i] = g_W1bf[i];
    } else {
        for (int s = tid; s < NC*ROWS*4; s += ROWS){
            const int c = s / (ROWS*4), rem = s % (ROWS*4);
            const int m = rem >> 2, o = rem & 3;
            const float* src = Asrc + (size_t)m*KA + c*32 + o*8;
            float f[8];
            *(float4*)&f[0] = __ldg((const float4*)src);
            *(float4*)&f[4] = __ldg((const float4*)(src + 4));
            uint4 H, L; cvt8(f, H, L);
            char* base = smem + OFF_SA + c*ROWS*128 + (m << 7);
            *(uint4*)(base + (uint32_t)(((o    ) ^ (m & 7)) << 4)) = H;
            *(uint4*)(base + (uint32_t)(((o + 4) ^ (m & 7)) << 4)) = L;
        }
    }
    __syncthreads();

    float acc[4][8][4];
    #pragma unroll
    for (int a = 0; a < 4; a++)
        #pragma unroll
        for (int b2 = 0; b2 < 8; b2++)
            #pragma unroll
            for (int c = 0; c < 4; c++) acc[a][b2][c] = 0.f;

    const int arow = m0 + (lane & 15);
    const int asel = lane >> 4;
    const int nrow0 = n0w + ((lane >> 4) << 3) + (lane & 7);
    const int bsel = (lane >> 3) & 1;

    #pragma unroll 1
    for (int p = 0; p < NPH; ++p){
        CVST_B(p);
        __syncthreads();
        if (p + 1 < NPH) PREF_B(p + 1);

        const int t = p & 1;
        const bool hion = LASTHI && (p == NPH - 1);
        const uint32_t sbA = sb + OFF_SA + (uint32_t)(p >> 1)*ROWS*128;
        const uint32_t sbB = sb + OFF_SB;
        uint32_t ah[4][4], al[4][4];
        #pragma unroll
        for (int mi = 0; mi < 4; mi++){
            const int row = arow + mi*16;
            const uint32_t base = sbA + ((uint32_t)row << 7);
            const int ch = 2*t + asel;
            ldm4(ah[mi], base + (uint32_t)(((ch    ) ^ (row & 7)) << 4));
            if (!hion)
                ldm4(al[mi], base + (uint32_t)(((ch + 4) ^ (row & 7)) << 4));
        }
        #pragma unroll
        for (int j = 0; j < 4; j++){
            const int n = nrow0 + j*16;
            const uint32_t nb = sbB + ((uint32_t)n << 7);
            const int ch = 2*t + bsel;
            uint32_t bh[4], bl[4];
            ldm4(bh, nb + (uint32_t)(((ch    ) ^ (n & 7)) << 4));
            #pragma unroll
            for (int mi = 0; mi < 4; mi++){
                mma_bf16(acc[mi][2*j],   ah[mi], bh + 0);
                mma_bf16(acc[mi][2*j+1], ah[mi], bh + 2);
            }
            if (!hion){
                #pragma unroll
                for (int mi = 0; mi < 4; mi++){
                    mma_bf16(acc[mi][2*j],   al[mi], bh + 0);
                    mma_bf16(acc[mi][2*j+1], al[mi], bh + 2);
                }
                ldm4(bl, nb + (uint32_t)(((ch + 4) ^ (n & 7)) << 4));
                #pragma unroll
                for (int mi = 0; mi < 4; mi++){
                    mma_bf16(acc[mi][2*j],   ah[mi], bl + 0);
                    mma_bf16(acc[mi][2*j+1], ah[mi], bl + 2);
                }
            }
        }
    }
    __syncthreads();

    // ---------------- epilogue: bias + BN partials + store/reduce ----------
    float* C = (float*)(smem + OFF_C);
    float2* P = (float2*)(smem + OFF_PART);   // [2 n-halves][ROWS]
    const int l4 = lane >> 2, lc = (lane & 3) << 1;
    float sr[8], s2r[8];
    #pragma unroll
    for (int i = 0; i < 8; i++){ sr[i] = 0.f; s2r[i] = 0.f; }
    #pragma unroll
    for (int mi = 0; mi < 4; mi++){
        const int r0 = m0 + mi*16 + l4;
        const float bv0 = bias[r0];
        const float bv1 = bias[r0 + 8];
        #pragma unroll
        for (int ni = 0; ni < 8; ni++){
            const int n = n0w + ni*8 + lc;
            float v0 = acc[mi][ni][0] + bv0, v1 = acc[mi][ni][1] + bv0;
            float v2 = acc[mi][ni][2] + bv1, v3 = acc[mi][ni][3] + bv1;
            *(float2*)&C[(size_t)r0*CPITCH + n]       = make_float2(v0, v1);
            *(float2*)&C[(size_t)(r0+8)*CPITCH + n]   = make_float2(v2, v3);
            sr[2*mi]   += v0 + v1;  s2r[2*mi]   += v0*v0 + v1*v1;
            sr[2*mi+1] += v2 + v3;  s2r[2*mi+1] += v2*v2 + v3*v3;
        }
    }
    #pragma unroll
    for (int o = 1; o <= 2; o <<= 1){
        #pragma unroll
        for (int i = 0; i < 8; i++){
            sr[i]  += __shfl_xor_sync(0xffffffffu, sr[i],  o);
            s2r[i] += __shfl_xor_sync(0xffffffffu, s2r[i], o);
        }
    }
    if ((lane & 3) == 0){
        #pragma unroll
        for (int mi = 0; mi < 4; mi++){
            P[(wid & 1)*ROWS + m0 + mi*16 + l4]     = make_float2(sr[2*mi],   s2r[2*mi]);
            P[(wid & 1)*ROWS + m0 + mi*16 + l4 + 8] = make_float2(sr[2*mi+1], s2r[2*mi+1]);
        }
    }
    __syncthreads();
    {
        const int r = tid;
        float2 p0 = P[r], p1 = P[ROWS + r];
        g_part[(size_t)r*NBLK + blockIdx.x] = make_float2(p0.x + p1.x, p0.y + p1.y);
    }
    if (FINAL){
        const int row = tid;
        #pragma unroll
        for (int g = 0; g < 4; g++){
            const float* src = C + (size_t)row*CPITCH + g*32;
            float mx = -3.4e38f, mn = 3.4e38f;
            #pragma unroll
            for (int k = 0; k < 32; k++){
                float v = src[k];
                mx = fmaxf(mx, v); mn = fminf(mn, v);
            }
            g_mm[(size_t)((cb >> 5) + g)*256 + row] = make_float2(mx, mn);
        }
    } else {
        const int n = tid;
        float* dst = Y + (size_t)(cb + n)*KSOUT;
        #pragma unroll 8
        for (int i = 0; i < 32; i++){
            float4 v;
            v.x = C[(size_t)(i*4 + 0)*CPITCH + n];
            v.y = C[(size_t)(i*4 + 1)*CPITCH + n];
            v.z = C[(size_t)(i*4 + 2)*CPITCH + n];
            v.w = C[(size_t)(i*4 + 3)*CPITCH + n];
            ((float4*)dst)[i] = v;
        }
    }
}

// -------------------- 5. finalize BN affine --------------------------------
__global__ void finalize_kernel(const float* __restrict__ gamma, const float* __restrict__ beta){
    const int c = blockIdx.x;
    float s = 0.f, s2 = 0.f;
    for (int i = threadIdx.x; i < NBLK; i += 256){
        float2 v = g_part[(size_t)c*NBLK + i];
        s += v.x; s2 += v.y;
    }
    #pragma unroll
    for (int o = 16; o > 0; o >>= 1){
        s  += __shfl_down_sync(0xffffffffu, s,  o);
        s2 += __shfl_down_sync(0xffffffffu, s2, o);
    }
    __shared__ float rs[8], rs2[8];
    int w = threadIdx.x >> 5, l = threadIdx.x & 31;
    if (l == 0){ rs[w] = s; rs2[w] = s2; }
    __syncthreads();
    if (threadIdx.x == 0){
        float S = 0.f, S2 = 0.f;
        #pragma unroll
        for (int i = 0; i < 8; i++){ S += rs[i]; S2 += rs2[i]; }
        float inv = 1.f/(float)COLSX;
        float mu  = S*inv;
        float var = fmaxf(S2*inv - mu*mu, 0.f);
        float a = gamma[c]*rsqrtf(var + 1e-5f);
        g_aff[c] = make_float2(a, beta[c] - a*mu);
    }
}

// -------------------- 6. final: affine + relu on (max|min) -----------------
__global__ __launch_bounds__(256) void finalmax_kernel(float* __restrict__ out){
    const int bm = blockIdx.x;
    const int b = bm >> 10, m = bm & 1023;
    const int co = threadIdx.x;
    const float2 af = g_aff[co];
    const float2 mm = g_mm[(size_t)bm*256 + co];
    const float v = (af.x >= 0.f) ? mm.x : mm.y;
    out[Bb*Mm*3 + (((size_t)(b*256 + co)) << 10) + m] = fmaxf(fmaf(af.x, v, af.y), 0.f);
}

// -------------------- launch ----------------------------------------------
#define SMEM_G1 (8192 + 5*128*128 + 16384)    // 106496
#define SMEM_G2 (8192 + 4*128*128 + 16384)    // 90112
#define SMEM_G3 (8192 + 4*256*128 + 16384)    // 155648

extern "C" void kernel_launch(void* const* d_in, const int* in_sizes, int n_in,
                              void* d_out, int out_size)
{
    const float* points_xyz = (const float*)d_in[0];
    const float* features   = (const float*)d_in[1];
    const int*   indices    = (const int*)  d_in[2];
    const float* w1 = (const float*)d_in[3];
    const float* b1 = (const float*)d_in[4];
    const float* g1 = (const float*)d_in[5];
    const float* be1= (const float*)d_in[6];
    const float* w2 = (const float*)d_in[7];
    const float* b2 = (const float*)d_in[8];
    const float* g2 = (const float*)d_in[9];
    const float* be2= (const float*)d_in[10];
    const float* w3 = (const float*)d_in[11];
    const float* b3 = (const float*)d_in[12];
    const float* g3 = (const float*)d_in[13];
    const float* be3= (const float*)d_in[14];
    float* out = (float*)d_out;

    float *Y1, *Y2;
    cudaGetSymbolAddress((void**)&Y1, g_Y1);
    cudaGetSymbolAddress((void**)&Y2, g_Y2);

    // ROWS, NPH, KA, KSOUT, ACT, GATHER, FINAL, AIMG, LASTHI
    auto* k1 = mma_gemm<128, 9, 128, 128, false, true,  false, true,  true >;
    auto* k2 = mma_gemm<128, 8, 128, 128, true,  false, false, false, false>;
    auto* k3 = mma_gemm<256, 8, 128, 0,   true,  false, true,  false, false>;
    cudaFuncSetAttribute(k1, cudaFuncAttributeMaxDynamicSharedMemorySize, SMEM_G1);
    cudaFuncSetAttribute(k2, cudaFuncAttributeMaxDynamicSharedMemorySize, SMEM_G2);
    cudaFuncSetAttribute(k3, cudaFuncAttributeMaxDynamicSharedMemorySize, SMEM_G3);

    // prep (2 launches)
    transpose_kernel<<<dim3(Nn/32, Cc/32, Bb), dim3(32,8)>>>(features);
    small_prep_kernel<<<(Bb*Nn + 255)/256, 256>>>(points_xyz, indices, w1, out);

    // ball query: 16 warps per query
    ballquery_kernel<<<Bb*Mm, 512>>>();

    // layer 1 (gather fused, W1 image resident, last phase hi-only)
    k1<<<NBLK, 128, SMEM_G1>>>(nullptr, nullptr, b1, Y1);
    finalize_kernel<<<128, 256>>>(g1, be1);

    // layer 2 (A-resident)
    k2<<<NBLK, 128, SMEM_G2>>>(w2, Y1, b2, Y2);
    finalize_kernel<<<128, 256>>>(g2, be2);

    // layer 3 (merged 256-row A-resident, K-max/min fused)
    k3<<<NBLK, 256, SMEM_G3>>>(w3, Y2, b3, nullptr);
    finalize_kernel<<<256, 256>>>(g3, be3);

    // final: affine + relu on reduced extrema
    finalmax_kernel<<<Bb*Mm, 256>>>(out);

    (void)in_sizes; (void)n_in; (void)out_size;
}

// round 11
// speedup vs baseline: 1.1302x; 1.1302x over previous
#include <cuda_runtime.h>
#include <cuda_bf16.h>
#include <cstdint>

// Problem constants
#define Bb 4
#define Nn 16384
#define Cc 128
#define Mm 1024
#define Kk 32
#define COLSX (Bb*Mm*Kk)          // 131072
#define R2c 0.16f
#define NBLK 1024                  // column tiles per GEMM (COLSX/128)

// -------------------- scratch (__device__ globals; no allocations) ---------
__device__ float  g_featT[(size_t)Bb*Nn*Cc];       // (B,N,C)
__device__ float4 g_xyz4[(size_t)Bb*Nn];           // packed xyz
__device__ float  g_newxyz[Bb*Mm*3];
__device__ int    g_idx[Bb*Mm*Kk];
__device__ float  g_W1p[128*128];                  // W1 feature part [cout][128]
__device__ float4 g_W1xyz4[128];                   // W1 xyz part [cout]
__device__ float  g_Y1[(size_t)COLSX*128];         // [col][cout]
__device__ float  g_Y2[(size_t)COLSX*128];
__device__ float2 g_mm[(size_t)Bb*Mm*256];         // [bm][cout] (max,min) over K
__device__ float2 g_part[(size_t)256*NBLK];
__device__ float2 g_aff[256];

// -------------------- helpers ----------------------------------------------
__device__ __forceinline__ uint32_t smem_u32(const void* p){
    uint32_t a;
    asm("{ .reg .u64 t; cvta.to.shared.u64 t, %1; cvt.u32.u64 %0, t; }" : "=r"(a) : "l"(p));
    return a;
}
__device__ __forceinline__ void ldm4(uint32_t* r, uint32_t addr){
    asm volatile("ldmatrix.sync.aligned.m8n8.x4.shared.b16 {%0,%1,%2,%3}, [%4];"
        : "=r"(r[0]), "=r"(r[1]), "=r"(r[2]), "=r"(r[3]) : "r"(addr));
}
__device__ __forceinline__ void mma_bf16(float* d, const uint32_t* a, const uint32_t* b){
    asm volatile("mma.sync.aligned.m16n8k16.row.col.f32.bf16.bf16.f32 "
        "{%0,%1,%2,%3}, {%4,%5,%6,%7}, {%8,%9}, {%0,%1,%2,%3};"
        : "+f"(d[0]), "+f"(d[1]), "+f"(d[2]), "+f"(d[3])
        : "r"(a[0]), "r"(a[1]), "r"(a[2]), "r"(a[3]), "r"(b[0]), "r"(b[1]));
}
// split 8 floats into hi/lo bf16 quads
__device__ __forceinline__ void cvt8(const float* f, uint4& H, uint4& L){
    uint32_t hh[4], ll[4];
    #pragma unroll
    for (int i = 0; i < 4; i++){
        __nv_bfloat162 h = __floats2bfloat162_rn(f[2*i], f[2*i+1]);
        float r0 = f[2*i]   - __low2float(h);
        float r1 = f[2*i+1] - __high2float(h);
        __nv_bfloat162 l = __floats2bfloat162_rn(r0, r1);
        hh[i] = *(uint32_t*)&h;
        ll[i] = *(uint32_t*)&l;
    }
    H = make_uint4(hh[0], hh[1], hh[2], hh[3]);
    L = make_uint4(ll[0], ll[1], ll[2], ll[3]);
}

// -------------------- 1. transpose features (B,C,N)->(B,N,C) ---------------
__global__ void transpose_kernel(const float* __restrict__ f){
    __shared__ float tile[32][33];
    const int b  = blockIdx.z;
    const int c0 = blockIdx.y << 5;
    const int n0 = blockIdx.x << 5;
    const int tx = threadIdx.x, ty = threadIdx.y;
    #pragma unroll
    for (int j = 0; j < 32; j += 8)
        tile[ty + j][tx] = f[((size_t)(b*Cc + c0 + ty + j))*Nn + n0 + tx];
    __syncthreads();
    #pragma unroll
    for (int j = 0; j < 32; j += 8)
        g_featT[((size_t)(b*Nn + n0 + ty + j))*Cc + c0 + tx] = tile[tx][ty + j];
}

// -------------------- 2. small prep: xyz4 + W1 split + newxyz --------------
__global__ void small_prep_kernel(const float* __restrict__ xyz,
                                  const int* __restrict__ indices,
                                  const float* __restrict__ w1,
                                  float* __restrict__ out){
    int t = blockIdx.x*256 + threadIdx.x;
    if (t < Bb*Nn){
        float4 v; v.x = xyz[t*3+0]; v.y = xyz[t*3+1]; v.z = xyz[t*3+2]; v.w = 0.f;
        g_xyz4[t] = v;
    }
    if (t < 128*128){
        int o = t >> 7, k = t & 127;
        g_W1p[t] = w1[o*131 + 3 + k];
    }
    if (t < 128){
        float4 v; v.x = w1[t*131+0]; v.y = w1[t*131+1]; v.z = w1[t*131+2]; v.w = 0.f;
        g_W1xyz4[t] = v;
    }
    if (t < Bb*Mm){
        int i = indices[t];
        const float* p = xyz + ((size_t)(t >> 10)*Nn + i)*3;
        float x = p[0], y = p[1], z = p[2];
        g_newxyz[t*3+0] = x; g_newxyz[t*3+1] = y; g_newxyz[t*3+2] = z;
        out[t*3+0] = x; out[t*3+1] = y; out[t*3+2] = z;
    }
}

// -------------------- 3. ball query: 16 warps/query + ordered merge --------
__global__ __launch_bounds__(512) void ballquery_kernel(){
    const int q = blockIdx.x;
    const int b = q >> 10;
    const int warp = threadIdx.x >> 5;
    const int lane = threadIdx.x & 31;
    __shared__ int cand[16][33];
    __shared__ int cnts[16];

    const float qx = g_newxyz[q*3+0];
    const float qy = g_newxyz[q*3+1];
    const float qz = g_newxyz[q*3+2];
    const float4* bp = g_xyz4 + (size_t)b*Nn;
    const int seg0 = warp << 10;

    int cnt = 0;
    for (int base = 0; base < 1024; base += 32){
        int n = seg0 + base + lane;
        float4 p = __ldg(bp + n);
        float dx = __fadd_rn(qx, -p.x), dy = __fadd_rn(qy, -p.y), dz = __fadd_rn(qz, -p.z);
        float d2 = __fadd_rn(__fadd_rn(__fmul_rn(dx,dx), __fmul_rn(dy,dy)), __fmul_rn(dz,dz));
        bool w = d2 < R2c;
        unsigned mask = __ballot_sync(0xffffffffu, w);
        int pre = __popc(mask & ((1u << lane) - 1u));
        if (w && cnt + pre < Kk) cand[warp][cnt + pre] = n;
        cnt += __popc(mask);
        if (cnt >= Kk) break;
    }
    if (lane == 0) cnts[warp] = cnt < Kk ? cnt : Kk;
    __syncthreads();

    if (warp == 0){
        int acc = 0, sel = -1, off = 0, first = -1;
        #pragma unroll
        for (int s = 0; s < 16; s++){
            int cs = cnts[s];
            if (sel < 0 && lane < acc + cs){ sel = s; off = lane - acc; }
            if (first < 0 && cs > 0) first = s;
            acc += cs;
        }
        int v = (sel >= 0) ? cand[sel][off]
                           : (first >= 0 ? cand[first][0] : 0);
        g_idx[q*Kk + lane] = v;
    }
}

// -------------------- 4. mma.sync bf16-split GEMM, 64x64 warp tiles --------
// 4 warps, block tile 128x128, warp tile 64x64.
// ARES: A (weights) converted ONCE into resident smem (per-chunk blocks);
//       mainloop streams only B through a double buffer.
// GATHER (gemm1): B from featT[ball-query idx]; the 3 xyz channels are a
//       rank-3 update applied EXACTLY in fp32 in the epilogue.
#define OFF_AFF  0
#define OFF_PART 1024
#define OFF_IDX  3072
#define OFF_XYZ  3584
#define OFF_WX   6144
#define OFF_SA   8192
#define OFF_C    8192
#define CPITCH   132

template<int KA, int NC, int KSOUT, bool ACT, bool GATHER, bool FINAL, bool ARES>
__global__ __launch_bounds__(128, 2)
void mma_gemm(const float* __restrict__ Asrc, const float* __restrict__ Bsrc,
              const float* __restrict__ bias, float* __restrict__ Y)
{
    constexpr int OFF_SB = ARES ? (OFF_SA + NC*16384) : (OFF_SA + 2*16384);
    extern __shared__ char smem[];
    const uint32_t sb = smem_u32(smem);
    const int tid = threadIdx.x, wid = tid >> 5, lane = tid & 31;
    const int cb = blockIdx.x << 7;
    const int rb = blockIdx.y << 7;
    const int m0  = (wid >> 1) << 6;    // warp m-base (64 rows)
    const int n0w = (wid & 1) << 6;     // warp n-base (64 cols)

    float* afs   = (float*)(smem + OFF_AFF);
    int*   sidx  = (int*)(smem + OFF_IDX);
    float4* sxyz = (float4*)(smem + OFF_XYZ);
    const size_t bBase = (size_t)(cb >> 15)*Nn;

    if (ACT) ((float2*)afs)[tid] = g_aff[tid];
    if (GATHER){
        int i = g_idx[cb + tid];
        sidx[tid] = i;
        float4 p = g_xyz4[bBase + i];
        const int bm = (cb + tid) >> 5;
        const float* q = g_newxyz + (size_t)bm*3;
        float4 r; r.x = p.x - q[0]; r.y = p.y - q[1]; r.z = p.z - q[2]; r.w = 0.f;
        sxyz[tid] = r;
        ((float4*)(smem + OFF_WX))[tid] = g_W1xyz4[tid];
    }
    if (ACT || GATHER) __syncthreads();

    float acc[4][8][4];
    #pragma unroll
    for (int a = 0; a < 4; a++)
        #pragma unroll
        for (int b2 = 0; b2 < 8; b2++)
            #pragma unroll
            for (int c = 0; c < 4; c++) acc[a][b2][c] = 0.f;

    float fB[4][8];                                 // prefetched B chunk

    auto PREF_B = [&](int c){
        const int k0 = c*32;
        #pragma unroll
        for (int it = 0; it < 4; it++){
            const int s = tid + it*128;
            const int n = s >> 2, oct = s & 3;
            const float* src = GATHER
                ? g_featT + ((bBase + (size_t)sidx[n]) << 7) + k0 + oct*8
                : Bsrc + (size_t)(cb + n)*KA + k0 + oct*8;
            *(float4*)&fB[it][0] = __ldg((const float4*)src);
            *(float4*)&fB[it][4] = __ldg((const float4*)(src + 4));
        }
    };
    auto CVST_A = [&](int c, char* SAb){
        const int k0 = c*32;
        #pragma unroll
        for (int it = 0; it < 4; it++){
            const int s = tid + it*128;
            const int m = s >> 2, oct = s & 3;
            const float* src = Asrc + (size_t)(rb + m)*KA + k0 + oct*8;
            float f[8];
            *(float4*)&f[0] = __ldg((const float4*)src);
            *(float4*)&f[4] = __ldg((const float4*)(src + 4));
            uint4 H, L; cvt8(f, H, L);
            const uint32_t ro = (uint32_t)m << 7;
            *(uint4*)(SAb + ro + (uint32_t)((oct       ^ (m & 7)) << 4)) = H;
            *(uint4*)(SAb + ro + (uint32_t)(((oct + 4) ^ (m & 7)) << 4)) = L;
        }
    };
    auto CVST_B = [&](int c){
        const int k0 = c*32;
        char* SBb = smem + OFF_SB + ((c & 1) << 14);
        #pragma unroll
        for (int it = 0; it < 4; it++){
            const int s = tid + it*128;
            const int n = s >> 2, oct = s & 3;
            float f[8];
            #pragma unroll
            for (int i = 0; i < 8; i++) f[i] = fB[it][i];
            if (ACT){
                #pragma unroll
                for (int i = 0; i < 8; i++){
                    const int k = k0 + oct*8 + i;
                    f[i] = fmaxf(fmaf(afs[2*k], f[i], afs[2*k+1]), 0.f);
                }
            }
            uint4 H, L; cvt8(f, H, L);
            const uint32_t ro = (uint32_t)n << 7;
            *(uint4*)(SBb + ro + (uint32_t)((oct       ^ (n & 7)) << 4)) = H;
            *(uint4*)(SBb + ro + (uint32_t)(((oct + 4) ^ (n & 7)) << 4)) = L;
        }
    };

    PREF_B(0);
    if (ARES){
        #pragma unroll
        for (int c = 0; c < NC; c++) CVST_A(c, smem + OFF_SA + c*16384);
    } else {
        CVST_A(0, smem + OFF_SA);
    }
    CVST_B(0);
    __syncthreads();

    const int arow = m0 + (lane & 15);
    const int asel = lane >> 4;
    const int nrow0 = n0w + ((lane >> 4) << 3) + (lane & 7);
    const int bsel = (lane >> 3) & 1;

    #pragma unroll 1
    for (int c = 0; c < NC; ++c){
        if (c + 1 < NC) PREF_B(c + 1);
        const uint32_t sbA = sb + OFF_SA + (ARES ? c*16384 : (c & 1) << 14);
        const uint32_t sbB = sb + OFF_SB + ((c & 1) << 14);
        #pragma unroll
        for (int t = 0; t < 2; t++){
            uint32_t ah[4][4], al[4][4];
            #pragma unroll
            for (int mi = 0; mi < 4; mi++){
                const int row = arow + mi*16;
                const uint32_t base = sbA + ((uint32_t)row << 7);
                const int ch = 2*t + asel;
                ldm4(ah[mi], base + (uint32_t)(((ch    ) ^ (row & 7)) << 4));
                ldm4(al[mi], base + (uint32_t)(((ch + 4) ^ (row & 7)) << 4));
            }
            #pragma unroll
            for (int j = 0; j < 4; j++){
                const int n = nrow0 + j*16;
                const uint32_t nb = sbB + ((uint32_t)n << 7);
                const int ch = 2*t + bsel;
                uint32_t bh[4], bl[4];
                ldm4(bh, nb + (uint32_t)(((ch    ) ^ (n & 7)) << 4));
                #pragma unroll
                for (int mi = 0; mi < 4; mi++){
                    mma_bf16(acc[mi][2*j],   ah[mi], bh + 0);
                    mma_bf16(acc[mi][2*j+1], ah[mi], bh + 2);
                }
                #pragma unroll
                for (int mi = 0; mi < 4; mi++){
                    mma_bf16(acc[mi][2*j],   al[mi], bh + 0);
                    mma_bf16(acc[mi][2*j+1], al[mi], bh + 2);
                }
                ldm4(bl, nb + (uint32_t)(((ch + 4) ^ (n & 7)) << 4));
                #pragma unroll
                for (int mi = 0; mi < 4; mi++){
                    mma_bf16(acc[mi][2*j],   ah[mi], bl + 0);
                    mma_bf16(acc[mi][2*j+1], ah[mi], bl + 2);
                }
            }
        }
        if (c + 1 < NC){
            if (!ARES) CVST_A(c + 1, smem + OFF_SA + (((c + 1) & 1) << 14));
            CVST_B(c + 1);
        }
        __syncthreads();
    }

    // ---------------- epilogue ---------------------------------------------
    float* C = (float*)(smem + OFF_C);
    float2* P = (float2*)(smem + OFF_PART);   // [4 warps][64 rows]
    const int l4 = lane >> 2, lc = (lane & 3) << 1;

    // exact fp32 rank-3 xyz update (gemm1 only)
    if (GATHER){
        const float4* wx4 = (const float4*)(smem + OFF_WX);
        #pragma unroll
        for (int mi = 0; mi < 4; mi++){
            const int r0 = m0 + mi*16 + l4;
            const float4 wA = wx4[r0];
            const float4 wB = wx4[r0 + 8];
            #pragma unroll
            for (int ni = 0; ni < 8; ni++){
                const int n = n0w + ni*8 + lc;
                const float4 p0 = sxyz[n], p1 = sxyz[n+1];
                acc[mi][ni][0] += wA.x*p0.x + wA.y*p0.y + wA.z*p0.z;
                acc[mi][ni][1] += wA.x*p1.x + wA.y*p1.y + wA.z*p1.z;
                acc[mi][ni][2] += wB.x*p0.x + wB.y*p0.y + wB.z*p0.z;
                acc[mi][ni][3] += wB.x*p1.x + wB.y*p1.y + wB.z*p1.z;
            }
        }
    }

    float sr[8], s2r[8];
    #pragma unroll
    for (int i = 0; i < 8; i++){ sr[i] = 0.f; s2r[i] = 0.f; }
    #pragma unroll
    for (int mi = 0; mi < 4; mi++){
        const int r0 = m0 + mi*16 + l4;
        const float bv0 = bias[rb + r0];
        const float bv1 = bias[rb + r0 + 8];
        #pragma unroll
        for (int ni = 0; ni < 8; ni++){
            const int n = n0w + ni*8 + lc;
            float v0 = acc[mi][ni][0] + bv0, v1 = acc[mi][ni][1] + bv0;
            float v2 = acc[mi][ni][2] + bv1, v3 = acc[mi][ni][3] + bv1;
            *(float2*)&C[(size_t)r0*CPITCH + n]       = make_float2(v0, v1);
            *(float2*)&C[(size_t)(r0+8)*CPITCH + n]   = make_float2(v2, v3);
            sr[2*mi]   += v0 + v1;  s2r[2*mi]   += v0*v0 + v1*v1;
            sr[2*mi+1] += v2 + v3;  s2r[2*mi+1] += v2*v2 + v3*v3;
        }
    }
    #pragma unroll
    for (int o = 1; o <= 2; o <<= 1){
        #pragma unroll
        for (int i = 0; i < 8; i++){
            sr[i]  += __shfl_xor_sync(0xffffffffu, sr[i],  o);
            s2r[i] += __shfl_xor_sync(0xffffffffu, s2r[i], o);
        }
    }
    if ((lane & 3) == 0){
        #pragma unroll
        for (int mi = 0; mi < 4; mi++){
            P[wid*64 + mi*16 + l4]     = make_float2(sr[2*mi],   s2r[2*mi]);
            P[wid*64 + mi*16 + l4 + 8] = make_float2(sr[2*mi+1], s2r[2*mi+1]);
        }
    }
    __syncthreads();
    {
        const int row = tid, wm = row >> 6, lr = row & 63;
        float2 p0 = P[(wm*2 + 0)*64 + lr], p1 = P[(wm*2 + 1)*64 + lr];
        g_part[(size_t)(rb + row)*NBLK + blockIdx.x] = make_float2(p0.x + p1.x, p0.y + p1.y);
    }
    if (FINAL){
        const int row = tid;
        #pragma unroll
        for (int g = 0; g < 4; g++){
            const float* src = C + (size_t)row*CPITCH + g*32;
            float mx = -3.4e38f, mn = 3.4e38f;
            #pragma unroll
            for (int k = 0; k < 32; k++){
                float v = src[k];
                mx = fmaxf(mx, v); mn = fminf(mn, v);
            }
            g_mm[(size_t)((cb >> 5) + g)*256 + rb + row] = make_float2(mx, mn);
        }
    } else {
        const int n = tid;
        float* dst = Y + (size_t)(cb + n)*KSOUT + rb;
        #pragma unroll 8
        for (int i = 0; i < 32; i++){
            float4 v;
            v.x = C[(size_t)(i*4 + 0)*CPITCH + n];
            v.y = C[(size_t)(i*4 + 1)*CPITCH + n];
            v.z = C[(size_t)(i*4 + 2)*CPITCH + n];
            v.w = C[(size_t)(i*4 + 3)*CPITCH + n];
            ((float4*)dst)[i] = v;
        }
    }
}

// -------------------- 5. finalize BN affine --------------------------------
__global__ void finalize_kernel(const float* __restrict__ gamma, const float* __restrict__ beta){
    const int c = blockIdx.x;
    float s = 0.f, s2 = 0.f;
    for (int i = threadIdx.x; i < NBLK; i += 256){
        float2 v = g_part[(size_t)c*NBLK + i];
        s += v.x; s2 += v.y;
    }
    #pragma unroll
    for (int o = 16; o > 0; o >>= 1){
        s  += __shfl_down_sync(0xffffffffu, s,  o);
        s2 += __shfl_down_sync(0xffffffffu, s2, o);
    }
    __shared__ float rs[8], rs2[8];
    int w = threadIdx.x >> 5, l = threadIdx.x & 31;
    if (l == 0){ rs[w] = s; rs2[w] = s2; }
    __syncthreads();
    if (threadIdx.x == 0){
        float S = 0.f, S2 = 0.f;
        #pragma unroll
        for (int i = 0; i < 8; i++){ S += rs[i]; S2 += rs2[i]; }
        float inv = 1.f/(float)COLSX;
        float mu  = S*inv;
        float var = fmaxf(S2*inv - mu*mu, 0.f);
        float a = gamma[c]*rsqrtf(var + 1e-5f);
        g_aff[c] = make_float2(a, beta[c] - a*mu);
    }
}

// -------------------- 6. final: affine + relu on (max|min) -----------------
__global__ __launch_bounds__(256) void finalmax_kernel(float* __restrict__ out){
    const int bm = blockIdx.x;
    const int b = bm >> 10, m = bm & 1023;
    const int co = threadIdx.x;
    const float2 af = g_aff[co];
    const float2 mm = g_mm[(size_t)bm*256 + co];
    const float v = (af.x >= 0.f) ? mm.x : mm.y;
    out[Bb*Mm*3 + (((size_t)(b*256 + co)) << 10) + m] = fmaxf(fmaf(af.x, v, af.y), 0.f);
}

// -------------------- launch ----------------------------------------------
#define SMEM_ARES (8192 + 4*16384 + 2*16384)   // 106496

extern "C" void kernel_launch(void* const* d_in, const int* in_sizes, int n_in,
                              void* d_out, int out_size)
{
    const float* points_xyz = (const float*)d_in[0];
    const float* features   = (const float*)d_in[1];
    const int*   indices    = (const int*)  d_in[2];
    const float* w1 = (const float*)d_in[3];
    const float* b1 = (const float*)d_in[4];
    const float* g1 = (const float*)d_in[5];
    const float* be1= (const float*)d_in[6];
    const float* w2 = (const float*)d_in[7];
    const float* b2 = (const float*)d_in[8];
    const float* g2 = (const float*)d_in[9];
    const float* be2= (const float*)d_in[10];
    const float* w3 = (const float*)d_in[11];
    const float* b3 = (const float*)d_in[12];
    const float* g3 = (const float*)d_in[13];
    const float* be3= (const float*)d_in[14];
    float* out = (float*)d_out;

    float *W1p, *Y1, *Y2;
    cudaGetSymbolAddress((void**)&W1p, g_W1p);
    cudaGetSymbolAddress((void**)&Y1,  g_Y1);
    cudaGetSymbolAddress((void**)&Y2,  g_Y2);

    // KA, NC, KSOUT, ACT, GATHER, FINAL, ARES
    auto* k1 = mma_gemm<128, 4, 128, false, true,  false, true>;
    auto* k2 = mma_gemm<128, 4, 128, true,  false, false, true>;
    auto* k3 = mma_gemm<128, 4, 256, true,  false, true,  true>;
    cudaFuncSetAttribute(k1, cudaFuncAttributeMaxDynamicSharedMemorySize, SMEM_ARES);
    cudaFuncSetAttribute(k2, cudaFuncAttributeMaxDynamicSharedMemorySize, SMEM_ARES);
    cudaFuncSetAttribute(k3, cudaFuncAttributeMaxDynamicSharedMemorySize, SMEM_ARES);

    // prep (2 launches)
    transpose_kernel<<<dim3(Nn/32, Cc/32, Bb), dim3(32,8)>>>(features);
    small_prep_kernel<<<(Bb*Nn + 255)/256, 256>>>(points_xyz, indices, w1, out);

    // ball query: 16 warps per query
    ballquery_kernel<<<Bb*Mm, 512>>>();

    // layer 1 (gather fused, A-resident, xyz as exact fp32 epilogue update)
    k1<<<dim3(NBLK, 1), 128, SMEM_ARES>>>(W1p, nullptr, b1, Y1);
    finalize_kernel<<<128, 256>>>(g1, be1);

    // layer 2 (A-resident)
    k2<<<dim3(NBLK, 1), 128, SMEM_ARES>>>(w2, Y1, b2, Y2);
    finalize_kernel<<<128, 256>>>(g2, be2);

    // layer 3 (A-resident, K-max/min fused)
    k3<<<dim3(NBLK, 2), 128, SMEM_ARES>>>(w3, Y2, b3, nullptr);
    finalize_kernel<<<256, 256>>>(g3, be3);

    // final: affine + relu on reduced extrema
    finalmax_kernel<<<Bb*Mm, 256>>>(out);

    (void)in_sizes; (void)n_in; (void)out_size;
}

// round 12
// speedup vs baseline: 1.2163x; 1.0762x over previous
#include <cuda_runtime.h>
#include <cuda_bf16.h>
#include <cstdint>

// Problem constants
#define Bb 4
#define Nn 16384
#define Cc 128
#define Mm 1024
#define Kk 32
#define COLSX (Bb*Mm*Kk)          // 131072
#define R2c 0.16f
#define NBLK 1024                  // column tiles per GEMM (COLSX/128)

// -------------------- scratch (__device__ globals; no allocations) ---------
__device__ float  g_featT[(size_t)Bb*Nn*Cc];       // (B,N,C)
__device__ float4 g_xyz4[(size_t)Bb*Nn];           // packed xyz
__device__ float  g_newxyz[Bb*Mm*3];
__device__ int    g_idx[Bb*Mm*Kk];
__device__ float  g_W1p[128*128];                  // W1 feature part [cout][128]
__device__ float4 g_W1xyz4[128];                   // W1 xyz part [cout]
__device__ float  g_Y1[(size_t)COLSX*128];         // [col][cout]
__device__ float  g_Y2[(size_t)COLSX*128];
__device__ float2 g_mm[(size_t)Bb*Mm*256];         // [bm][cout] (max,min) over K
__device__ float2 g_part[(size_t)256*NBLK];
__device__ float2 g_aff[256];

// -------------------- helpers ----------------------------------------------
__device__ __forceinline__ uint32_t smem_u32(const void* p){
    uint32_t a;
    asm("{ .reg .u64 t; cvta.to.shared.u64 t, %1; cvt.u32.u64 %0, t; }" : "=r"(a) : "l"(p));
    return a;
}
__device__ __forceinline__ void ldm4(uint32_t* r, uint32_t addr){
    asm volatile("ldmatrix.sync.aligned.m8n8.x4.shared.b16 {%0,%1,%2,%3}, [%4];"
        : "=r"(r[0]), "=r"(r[1]), "=r"(r[2]), "=r"(r[3]) : "r"(addr));
}
__device__ __forceinline__ void mma_bf16(float* d, const uint32_t* a, const uint32_t* b){
    asm volatile("mma.sync.aligned.m16n8k16.row.col.f32.bf16.bf16.f32 "
        "{%0,%1,%2,%3}, {%4,%5,%6,%7}, {%8,%9}, {%0,%1,%2,%3};"
        : "+f"(d[0]), "+f"(d[1]), "+f"(d[2]), "+f"(d[3])
        : "r"(a[0]), "r"(a[1]), "r"(a[2]), "r"(a[3]), "r"(b[0]), "r"(b[1]));
}
// split 8 floats into hi/lo bf16 quads
__device__ __forceinline__ void cvt8(const float* f, uint4& H, uint4& L){
    uint32_t hh[4], ll[4];
    #pragma unroll
    for (int i = 0; i < 4; i++){
        __nv_bfloat162 h = __floats2bfloat162_rn(f[2*i], f[2*i+1]);
        float r0 = f[2*i]   - __low2float(h);
        float r1 = f[2*i+1] - __high2float(h);
        __nv_bfloat162 l = __floats2bfloat162_rn(r0, r1);
        hh[i] = *(uint32_t*)&h;
        ll[i] = *(uint32_t*)&l;
    }
    H = make_uint4(hh[0], hh[1], hh[2], hh[3]);
    L = make_uint4(ll[0], ll[1], ll[2], ll[3]);
}

// -------------------- 1. transpose features (B,C,N)->(B,N,C) ---------------
__global__ void transpose_kernel(const float* __restrict__ f){
    __shared__ float tile[32][33];
    const int b  = blockIdx.z;
    const int c0 = blockIdx.y << 5;
    const int n0 = blockIdx.x << 5;
    const int tx = threadIdx.x, ty = threadIdx.y;
    #pragma unroll
    for (int j = 0; j < 32; j += 8)
        tile[ty + j][tx] = f[((size_t)(b*Cc + c0 + ty + j))*Nn + n0 + tx];
    __syncthreads();
    #pragma unroll
    for (int j = 0; j < 32; j += 8)
        g_featT[((size_t)(b*Nn + n0 + ty + j))*Cc + c0 + tx] = tile[tx][ty + j];
}

// -------------------- 2. small prep: xyz4 + W1 split + newxyz --------------
__global__ void small_prep_kernel(const float* __restrict__ xyz,
                                  const int* __restrict__ indices,
                                  const float* __restrict__ w1,
                                  float* __restrict__ out){
    int t = blockIdx.x*256 + threadIdx.x;
    if (t < Bb*Nn){
        float4 v; v.x = xyz[t*3+0]; v.y = xyz[t*3+1]; v.z = xyz[t*3+2]; v.w = 0.f;
        g_xyz4[t] = v;
    }
    if (t < 128*128){
        int o = t >> 7, k = t & 127;
        g_W1p[t] = w1[o*131 + 3 + k];
    }
    if (t < 128){
        float4 v; v.x = w1[t*131+0]; v.y = w1[t*131+1]; v.z = w1[t*131+2]; v.w = 0.f;
        g_W1xyz4[t] = v;
    }
    if (t < Bb*Mm){
        int i = indices[t];
        const float* p = xyz + ((size_t)(t >> 10)*Nn + i)*3;
        float x = p[0], y = p[1], z = p[2];
        g_newxyz[t*3+0] = x; g_newxyz[t*3+1] = y; g_newxyz[t*3+2] = z;
        out[t*3+0] = x; out[t*3+1] = y; out[t*3+2] = z;
    }
}

// -------------------- 3. ball query: adaptive round-based scan -------------
// Each round: 16 warps jointly cover one 2048-index window (128 pts/warp),
// then warp 0 merges the round's hits in global index order into a running
// list; the block exits once 32 are collected. Semantics identical to the
// reference ordered-first-k (rounds are index-ordered, segments ordered
// within a round, ballot order within a segment).
__global__ __launch_bounds__(512) void ballquery_kernel(){
    const int q = blockIdx.x;
    const int b = q >> 10;
    const int warp = threadIdx.x >> 5;
    const int lane = threadIdx.x & 31;
    __shared__ int cand[16][33];
    __shared__ int cnts[16];
    __shared__ int glist[32];
    __shared__ int gstate[2];      // [0]=collected total, [1]=first index (-1 none)

    if (threadIdx.x == 0){ gstate[0] = 0; gstate[1] = -1; }

    const float qx = g_newxyz[q*3+0];
    const float qy = g_newxyz[q*3+1];
    const float qz = g_newxyz[q*3+2];
    const float4* bp = g_xyz4 + (size_t)b*Nn;

    for (int r = 0; r < 8; r++){
        const int segbase = (r << 11) + (warp << 7);
        int cnt = 0;
        #pragma unroll
        for (int it = 0; it < 4; it++){
            int n = segbase + it*32 + lane;
            float4 p = __ldg(bp + n);
            float dx = __fadd_rn(qx, -p.x), dy = __fadd_rn(qy, -p.y), dz = __fadd_rn(qz, -p.z);
            float d2 = __fadd_rn(__fadd_rn(__fmul_rn(dx,dx), __fmul_rn(dy,dy)), __fmul_rn(dz,dz));
            bool w = d2 < R2c;
            unsigned mask = __ballot_sync(0xffffffffu, w);
            int pre = __popc(mask & ((1u << lane) - 1u));
            if (w && cnt + pre < Kk) cand[warp][cnt + pre] = n;
            cnt += __popc(mask);
        }
        if (lane == 0) cnts[warp] = cnt < Kk ? cnt : Kk;
        __syncthreads();

        if (warp == 0){
            const int base = gstate[0];
            const int rel = lane - base;       // slot within this round's stream
            int acc = 0, sel = -1, off = 0, firstseg = -1;
            #pragma unroll
            for (int s = 0; s < 16; s++){
                int cs = cnts[s];
                if (sel < 0 && rel >= 0 && rel < acc + cs){ sel = s; off = rel - acc; }
                if (firstseg < 0 && cs > 0) firstseg = s;
                acc += cs;
            }
            if (sel >= 0 && lane < Kk) glist[lane] = cand[sel][off];
            if (lane == 0){
                if (gstate[1] < 0 && firstseg >= 0) gstate[1] = cand[firstseg][0];
                int nt = base + acc;
                gstate[0] = nt > Kk ? Kk : nt;
            }
        }
        __syncthreads();
        if (gstate[0] >= Kk) break;
    }

    if (warp == 0){
        const int gtot = gstate[0];
        const int gf = gstate[1];
        int v = (lane < gtot) ? glist[lane] : (gf >= 0 ? gf : 0);
        g_idx[q*Kk + lane] = v;
    }
}

// -------------------- 4. mma.sync bf16-split GEMM, 64x64 warp tiles --------
// 4 warps, block tile 128x128, warp tile 64x64.
// ARES: A (weights) converted ONCE into resident smem (per-chunk blocks);
//       mainloop streams only B through a double buffer.
// GATHER (gemm1): B from featT[ball-query idx]; the 3 xyz channels are a
//       rank-3 update applied EXACTLY in fp32 in the epilogue.
#define OFF_AFF  0
#define OFF_PART 1024
#define OFF_IDX  3072
#define OFF_XYZ  3584
#define OFF_WX   6144
#define OFF_SA   8192
#define OFF_C    8192
#define CPITCH   132

template<int KA, int NC, int KSOUT, bool ACT, bool GATHER, bool FINAL, bool ARES>
__global__ __launch_bounds__(128, 2)
void mma_gemm(const float* __restrict__ Asrc, const float* __restrict__ Bsrc,
              const float* __restrict__ bias, float* __restrict__ Y)
{
    constexpr int OFF_SB = ARES ? (OFF_SA + NC*16384) : (OFF_SA + 2*16384);
    extern __shared__ char smem[];
    const uint32_t sb = smem_u32(smem);
    const int tid = threadIdx.x, wid = tid >> 5, lane = tid & 31;
    const int cb = blockIdx.x << 7;
    const int rb = blockIdx.y << 7;
    const int m0  = (wid >> 1) << 6;    // warp m-base (64 rows)
    const int n0w = (wid & 1) << 6;     // warp n-base (64 cols)

    float* afs   = (float*)(smem + OFF_AFF);
    int*   sidx  = (int*)(smem + OFF_IDX);
    float4* sxyz = (float4*)(smem + OFF_XYZ);
    const size_t bBase = (size_t)(cb >> 15)*Nn;

    if (ACT) ((float2*)afs)[tid] = g_aff[tid];
    if (GATHER){
        int i = g_idx[cb + tid];
        sidx[tid] = i;
        float4 p = g_xyz4[bBase + i];
        const int bm = (cb + tid) >> 5;
        const float* q = g_newxyz + (size_t)bm*3;
        float4 r; r.x = p.x - q[0]; r.y = p.y - q[1]; r.z = p.z - q[2]; r.w = 0.f;
        sxyz[tid] = r;
        ((float4*)(smem + OFF_WX))[tid] = g_W1xyz4[tid];
    }
    if (ACT || GATHER) __syncthreads();

    float acc[4][8][4];
    #pragma unroll
    for (int a = 0; a < 4; a++)
        #pragma unroll
        for (int b2 = 0; b2 < 8; b2++)
            #pragma unroll
            for (int c = 0; c < 4; c++) acc[a][b2][c] = 0.f;

    float fB[4][8];                                 // prefetched B chunk

    auto PREF_B = [&](int c){
        const int k0 = c*32;
        #pragma unroll
        for (int it = 0; it < 4; it++){
            const int s = tid + it*128;
            const int n = s >> 2, oct = s & 3;
            const float* src = GATHER
                ? g_featT + ((bBase + (size_t)sidx[n]) << 7) + k0 + oct*8
                : Bsrc + (size_t)(cb + n)*KA + k0 + oct*8;
            *(float4*)&fB[it][0] = __ldg((const float4*)src);
            *(float4*)&fB[it][4] = __ldg((const float4*)(src + 4));
        }
    };
    auto CVST_A = [&](int c, char* SAb){
        const int k0 = c*32;
        #pragma unroll
        for (int it = 0; it < 4; it++){
            const int s = tid + it*128;
            const int m = s >> 2, oct = s & 3;
            const float* src = Asrc + (size_t)(rb + m)*KA + k0 + oct*8;
            float f[8];
            *(float4*)&f[0] = __ldg((const float4*)src);
            *(float4*)&f[4] = __ldg((const float4*)(src + 4));
            uint4 H, L; cvt8(f, H, L);
            const uint32_t ro = (uint32_t)m << 7;
            *(uint4*)(SAb + ro + (uint32_t)((oct       ^ (m & 7)) << 4)) = H;
            *(uint4*)(SAb + ro + (uint32_t)(((oct + 4) ^ (m & 7)) << 4)) = L;
        }
    };
    auto CVST_B = [&](int c){
        const int k0 = c*32;
        char* SBb = smem + OFF_SB + ((c & 1) << 14);
        #pragma unroll
        for (int it = 0; it < 4; it++){
            const int s = tid + it*128;
            const int n = s >> 2, oct = s & 3;
            float f[8];
            #pragma unroll
            for (int i = 0; i < 8; i++) f[i] = fB[it][i];
            if (ACT){
                #pragma unroll
                for (int i = 0; i < 8; i++){
                    const int k = k0 + oct*8 + i;
                    f[i] = fmaxf(fmaf(afs[2*k], f[i], afs[2*k+1]), 0.f);
                }
            }
            uint4 H, L; cvt8(f, H, L);
            const uint32_t ro = (uint32_t)n << 7;
            *(uint4*)(SBb + ro + (uint32_t)((oct       ^ (n & 7)) << 4)) = H;
            *(uint4*)(SBb + ro + (uint32_t)(((oct + 4) ^ (n & 7)) << 4)) = L;
        }
    };

    PREF_B(0);
    if (ARES){
        #pragma unroll
        for (int c = 0; c < NC; c++) CVST_A(c, smem + OFF_SA + c*16384);
    } else {
        CVST_A(0, smem + OFF_SA);
    }
    CVST_B(0);
    __syncthreads();

    const int arow = m0 + (lane & 15);
    const int asel = lane >> 4;
    const int nrow0 = n0w + ((lane >> 4) << 3) + (lane & 7);
    const int bsel = (lane >> 3) & 1;

    #pragma unroll 1
    for (int c = 0; c < NC; ++c){
        if (c + 1 < NC) PREF_B(c + 1);
        const uint32_t sbA = sb + OFF_SA + (ARES ? c*16384 : (c & 1) << 14);
        const uint32_t sbB = sb + OFF_SB + ((c & 1) << 14);
        #pragma unroll
        for (int t = 0; t < 2; t++){
            uint32_t ah[4][4], al[4][4];
            #pragma unroll
            for (int mi = 0; mi < 4; mi++){
                const int row = arow + mi*16;
                const uint32_t base = sbA + ((uint32_t)row << 7);
                const int ch = 2*t + asel;
                ldm4(ah[mi], base + (uint32_t)(((ch    ) ^ (row & 7)) << 4));
                ldm4(al[mi], base + (uint32_t)(((ch + 4) ^ (row & 7)) << 4));
            }
            #pragma unroll
            for (int j = 0; j < 4; j++){
                const int n = nrow0 + j*16;
                const uint32_t nb = sbB + ((uint32_t)n << 7);
                const int ch = 2*t + bsel;
                uint32_t bh[4], bl[4];
                ldm4(bh, nb + (uint32_t)(((ch    ) ^ (n & 7)) << 4));
                #pragma unroll
                for (int mi = 0; mi < 4; mi++){
                    mma_bf16(acc[mi][2*j],   ah[mi], bh + 0);
                    mma_bf16(acc[mi][2*j+1], ah[mi], bh + 2);
                }
                #pragma unroll
                for (int mi = 0; mi < 4; mi++){
                    mma_bf16(acc[mi][2*j],   al[mi], bh + 0);
                    mma_bf16(acc[mi][2*j+1], al[mi], bh + 2);
                }
                ldm4(bl, nb + (uint32_t)(((ch + 4) ^ (n & 7)) << 4));
                #pragma unroll
                for (int mi = 0; mi < 4; mi++){
                    mma_bf16(acc[mi][2*j],   ah[mi], bl + 0);
                    mma_bf16(acc[mi][2*j+1], ah[mi], bl + 2);
                }
            }
        }
        if (c + 1 < NC){
            if (!ARES) CVST_A(c + 1, smem + OFF_SA + (((c + 1) & 1) << 14));
            CVST_B(c + 1);
        }
        __syncthreads();
    }

    // ---------------- epilogue ---------------------------------------------
    float* C = (float*)(smem + OFF_C);
    float2* P = (float2*)(smem + OFF_PART);   // [4 warps][64 rows]
    const int l4 = lane >> 2, lc = (lane & 3) << 1;

    // exact fp32 rank-3 xyz update (gemm1 only)
    if (GATHER){
        const float4* wx4 = (const float4*)(smem + OFF_WX);
        #pragma unroll
        for (int mi = 0; mi < 4; mi++){
            const int r0 = m0 + mi*16 + l4;
            const float4 wA = wx4[r0];
            const float4 wB = wx4[r0 + 8];
            #pragma unroll
            for (int ni = 0; ni < 8; ni++){
                const int n = n0w + ni*8 + lc;
                const float4 p0 = sxyz[n], p1 = sxyz[n+1];
                acc[mi][ni][0] += wA.x*p0.x + wA.y*p0.y + wA.z*p0.z;
                acc[mi][ni][1] += wA.x*p1.x + wA.y*p1.y + wA.z*p1.z;
                acc[mi][ni][2] += wB.x*p0.x + wB.y*p0.y + wB.z*p0.z;
                acc[mi][ni][3] += wB.x*p1.x + wB.y*p1.y + wB.z*p1.z;
            }
        }
    }

    float sr[8], s2r[8];
    #pragma unroll
    for (int i = 0; i < 8; i++){ sr[i] = 0.f; s2r[i] = 0.f; }
    #pragma unroll
    for (int mi = 0; mi < 4; mi++){
        const int r0 = m0 + mi*16 + l4;
        const float bv0 = bias[rb + r0];
        const float bv1 = bias[rb + r0 + 8];
        #pragma unroll
        for (int ni = 0; ni < 8; ni++){
            const int n = n0w + ni*8 + lc;
            float v0 = acc[mi][ni][0] + bv0, v1 = acc[mi][ni][1] + bv0;
            float v2 = acc[mi][ni][2] + bv1, v3 = acc[mi][ni][3] + bv1;
            *(float2*)&C[(size_t)r0*CPITCH + n]       = make_float2(v0, v1);
            *(float2*)&C[(size_t)(r0+8)*CPITCH + n]   = make_float2(v2, v3);
            sr[2*mi]   += v0 + v1;  s2r[2*mi]   += v0*v0 + v1*v1;
            sr[2*mi+1] += v2 + v3;  s2r[2*mi+1] += v2*v2 + v3*v3;
        }
    }
    #pragma unroll
    for (int o = 1; o <= 2; o <<= 1){
        #pragma unroll
        for (int i = 0; i < 8; i++){
            sr[i]  += __shfl_xor_sync(0xffffffffu, sr[i],  o);
            s2r[i] += __shfl_xor_sync(0xffffffffu, s2r[i], o);
        }
    }
    if ((lane & 3) == 0){
        #pragma unroll
        for (int mi = 0; mi < 4; mi++){
            P[wid*64 + mi*16 + l4]     = make_float2(sr[2*mi],   s2r[2*mi]);
            P[wid*64 + mi*16 + l4 + 8] = make_float2(sr[2*mi+1], s2r[2*mi+1]);
        }
    }
    __syncthreads();
    {
        const int row = tid, wm = row >> 6, lr = row & 63;
        float2 p0 = P[(wm*2 + 0)*64 + lr], p1 = P[(wm*2 + 1)*64 + lr];
        g_part[(size_t)(rb + row)*NBLK + blockIdx.x] = make_float2(p0.x + p1.x, p0.y + p1.y);
    }
    if (FINAL){
        const int row = tid;
        #pragma unroll
        for (int g = 0; g < 4; g++){
            const float* src = C + (size_t)row*CPITCH + g*32;
            float mx = -3.4e38f, mn = 3.4e38f;
            #pragma unroll
            for (int k = 0; k < 32; k++){
                float v = src[k];
                mx = fmaxf(mx, v); mn = fminf(mn, v);
            }
            g_mm[(size_t)((cb >> 5) + g)*256 + rb + row] = make_float2(mx, mn);
        }
    } else {
        const int n = tid;
        float* dst = Y + (size_t)(cb + n)*KSOUT + rb;
        #pragma unroll 8
        for (int i = 0; i < 32; i++){
            float4 v;
            v.x = C[(size_t)(i*4 + 0)*CPITCH + n];
            v.y = C[(size_t)(i*4 + 1)*CPITCH + n];
            v.z = C[(size_t)(i*4 + 2)*CPITCH + n];
            v.w = C[(size_t)(i*4 + 3)*CPITCH + n];
            ((float4*)dst)[i] = v;
        }
    }
}

// -------------------- 5. finalize BN affine --------------------------------
__global__ void finalize_kernel(const float* __restrict__ gamma, const float* __restrict__ beta){
    const int c = blockIdx.x;
    float s = 0.f, s2 = 0.f;
    for (int i = threadIdx.x; i < NBLK; i += 256){
        float2 v = g_part[(size_t)c*NBLK + i];
        s += v.x; s2 += v.y;
    }
    #pragma unroll
    for (int o = 16; o > 0; o >>= 1){
        s  += __shfl_down_sync(0xffffffffu, s,  o);
        s2 += __shfl_down_sync(0xffffffffu, s2, o);
    }
    __shared__ float rs[8], rs2[8];
    int w = threadIdx.x >> 5, l = threadIdx.x & 31;
    if (l == 0){ rs[w] = s; rs2[w] = s2; }
    __syncthreads();
    if (threadIdx.x == 0){
        float S = 0.f, S2 = 0.f;
        #pragma unroll
        for (int i = 0; i < 8; i++){ S += rs[i]; S2 += rs2[i]; }
        float inv = 1.f/(float)COLSX;
        float mu  = S*inv;
        float var = fmaxf(S2*inv - mu*mu, 0.f);
        float a = gamma[c]*rsqrtf(var + 1e-5f);
        g_aff[c] = make_float2(a, beta[c] - a*mu);
    }
}

// -------------------- 6. final: affine + relu on (max|min) -----------------
__global__ __launch_bounds__(256) void finalmax_kernel(float* __restrict__ out){
    const int bm = blockIdx.x;
    const int b = bm >> 10, m = bm & 1023;
    const int co = threadIdx.x;
    const float2 af = g_aff[co];
    const float2 mm = g_mm[(size_t)bm*256 + co];
    const float v = (af.x >= 0.f) ? mm.x : mm.y;
    out[Bb*Mm*3 + (((size_t)(b*256 + co)) << 10) + m] = fmaxf(fmaf(af.x, v, af.y), 0.f);
}

// -------------------- launch ----------------------------------------------
#define SMEM_ARES (8192 + 4*16384 + 2*16384)   // 106496

extern "C" void kernel_launch(void* const* d_in, const int* in_sizes, int n_in,
                              void* d_out, int out_size)
{
    const float* points_xyz = (const float*)d_in[0];
    const float* features   = (const float*)d_in[1];
    const int*   indices    = (const int*)  d_in[2];
    const float* w1 = (const float*)d_in[3];
    const float* b1 = (const float*)d_in[4];
    const float* g1 = (const float*)d_in[5];
    const float* be1= (const float*)d_in[6];
    const float* w2 = (const float*)d_in[7];
    const float* b2 = (const float*)d_in[8];
    const float* g2 = (const float*)d_in[9];
    const float* be2= (const float*)d_in[10];
    const float* w3 = (const float*)d_in[11];
    const float* b3 = (const float*)d_in[12];
    const float* g3 = (const float*)d_in[13];
    const float* be3= (const float*)d_in[14];
    float* out = (float*)d_out;

    float *W1p, *Y1, *Y2;
    cudaGetSymbolAddress((void**)&W1p, g_W1p);
    cudaGetSymbolAddress((void**)&Y1,  g_Y1);
    cudaGetSymbolAddress((void**)&Y2,  g_Y2);

    // KA, NC, KSOUT, ACT, GATHER, FINAL, ARES
    auto* k1 = mma_gemm<128, 4, 128, false, true,  false, true>;
    auto* k2 = mma_gemm<128, 4, 128, true,  false, false, true>;
    auto* k3 = mma_gemm<128, 4, 256, true,  false, true,  true>;
    cudaFuncSetAttribute(k1, cudaFuncAttributeMaxDynamicSharedMemorySize, SMEM_ARES);
    cudaFuncSetAttribute(k2, cudaFuncAttributeMaxDynamicSharedMemorySize, SMEM_ARES);
    cudaFuncSetAttribute(k3, cudaFuncAttributeMaxDynamicSharedMemorySize, SMEM_ARES);

    // prep (2 launches)
    transpose_kernel<<<dim3(Nn/32, Cc/32, Bb), dim3(32,8)>>>(features);
    small_prep_kernel<<<(Bb*Nn + 255)/256, 256>>>(points_xyz, indices, w1, out);

    // ball query: adaptive round-based (early exit at 32 collected)
    ballquery_kernel<<<Bb*Mm, 512>>>();

    // layer 1 (gather fused, A-resident, xyz as exact fp32 epilogue update)
    k1<<<dim3(NBLK, 1), 128, SMEM_ARES>>>(W1p, nullptr, b1, Y1);
    finalize_kernel<<<128, 256>>>(g1, be1);

    // layer 2 (A-resident)
    k2<<<dim3(NBLK, 1), 128, SMEM_ARES>>>(w2, Y1, b2, Y2);
    finalize_kernel<<<128, 256>>>(g2, be2);

    // layer 3 (A-resident, K-max/min fused)
    k3<<<dim3(NBLK, 2), 128, SMEM_ARES>>>(w3, Y2, b3, nullptr);
    finalize_kernel<<<256, 256>>>(g3, be3);

    // final: affine + relu on reduced extrema
    finalmax_kernel<<<Bb*Mm, 256>>>(out);

    (void)in_sizes; (void)n_in; (void)out_size;
}